// round 11
// baseline (speedup 1.0000x reference)
#include <cuda_runtime.h>
#include <math.h>
#include <stdint.h>

#define BB   32
#define SS   256
#define NN   50
#define DD   100
#define QDIM 768

#define NT   13      // n-tiles over 104 cols = 100 v-rows (2 s) + 4 pad
#define KT   13      // k-tiles over 104 (100 used)
#define AP   108     // v-tile row stride (floats), conflict-free
#define PAIRS_PER_BLK 2
#define AF_PER_B (7 * KT * 128)   // floats per batch in g_Af = 11648

__device__ float g_Qraw[BB * DD];
__device__ float g_cb[BB];
__device__ float g_Af[BB * AF_PER_B];   // A-frags of [W; w~] : [b][w][kt][lane][4]
__device__ float g_T[BB * SS * DD];     // t = att @ v (exact fp32)
__device__ float g_sig[BB * SS];        // sum of final att per row

// ---------------------------------------------------------------------------
__device__ __forceinline__ void mma_tf32(float c[4], const float* a,
                                         float b0, float b1)
{
    asm volatile(
        "mma.sync.aligned.m16n8k8.row.col.f32.tf32.tf32.f32 "
        "{%0,%1,%2,%3}, {%4,%5,%6,%7}, {%8,%9}, {%0,%1,%2,%3};\n"
        : "+f"(c[0]), "+f"(c[1]), "+f"(c[2]), "+f"(c[3])
        : "r"(__float_as_uint(a[0])), "r"(__float_as_uint(a[1])),
          "r"(__float_as_uint(a[2])), "r"(__float_as_uint(a[3])),
          "r"(__float_as_uint(b0)),  "r"(__float_as_uint(b1)));
}

// ---------------------------------------------------------------------------
// Kernel 1a: g_Qraw[b][e] = q[b] . Qw[e] + Qb[e]
// ---------------------------------------------------------------------------
__global__ __launch_bounds__(128) void qproj_a(
    const float* __restrict__ q,
    const float* __restrict__ Qw,
    const float* __restrict__ Qb)
{
    int b = blockIdx.x / DD, e = blockIdx.x % DD;
    __shared__ float red[4];
    const float* qr = q + (size_t)b * QDIM;
    const float* wr = Qw + (size_t)e * QDIM;
    int tid = threadIdx.x, warp = tid >> 5, lane = tid & 31;

    float acc = 0.f;
    #pragma unroll 6
    for (int i = tid; i < QDIM; i += 128) acc += qr[i] * wr[i];
    #pragma unroll
    for (int o = 16; o; o >>= 1) acc += __shfl_xor_sync(0xffffffffu, acc, o);
    if (lane == 0) red[warp] = acc;
    __syncthreads();
    if (tid == 0)
        g_Qraw[b * DD + e] = red[0] + red[1] + red[2] + red[3] + Qb[e];
}

// ---------------------------------------------------------------------------
// Kernel 1b: per batch: normalize Q, w~ = Vw^T Qn, cb = Qn.Vb, build A frags
// A GEMM rows: 0..99 = W rows, 100 = w~, 101..111 = 0; cols >= 100 -> 0
// ---------------------------------------------------------------------------
__global__ __launch_bounds__(128) void qproj_b(
    const float* __restrict__ Vw,
    const float* __restrict__ Vb)
{
    int b = blockIdx.x;
    __shared__ float sQ[DD];
    __shared__ float sWq[DD];
    __shared__ float red[4];

    int tid = threadIdx.x, warp = tid >> 5, lane = tid & 31;

    float qv = (tid < DD) ? g_Qraw[b * DD + tid] : 0.f;
    float ss = qv * qv;
    #pragma unroll
    for (int o = 16; o; o >>= 1) ss += __shfl_xor_sync(0xffffffffu, ss, o);
    if (lane == 0) red[warp] = ss;
    __syncthreads();
    if (tid == 0)
        red[0] = fmaxf(sqrtf(red[0] + red[1] + red[2] + red[3]), 1e-12f);
    __syncthreads();
    float inv = 1.0f / red[0];
    if (tid < DD) sQ[tid] = qv * inv;
    __syncthreads();

    if (tid < DD) {
        float a = 0.f;
        #pragma unroll 4
        for (int e = 0; e < DD; e++) a += sQ[e] * Vw[e * DD + tid];
        sWq[tid] = a;
    }
    if (warp == 0) {
        float a = 0.f;
        for (int e = lane; e < DD; e += 32) a += sQ[e] * Vb[e];
        #pragma unroll
        for (int o = 16; o; o >>= 1) a += __shfl_xor_sync(0xffffffffu, a, o);
        if (lane == 0) g_cb[b] = a;
    }
    __syncthreads();

    float* dst = g_Af + (size_t)b * AF_PER_B;
    for (int i = tid; i < 7 * KT * 32; i += 128) {
        int ln = i & 31;
        int kt = (i >> 5) % KT;
        int w  = (i >> 5) / KT;
        int g = ln >> 2, tg = ln & 3;
        int m0 = w * 16 + g, m1 = m0 + 8;
        int k0 = kt * 8 + tg, k1 = k0 + 4;
        float a0 = 0.f, a1 = 0.f, a2 = 0.f, a3 = 0.f;
        if (m0 < 100) {
            if (k0 < 100) a0 = Vw[m0 * DD + k0];
            if (k1 < 100) a2 = Vw[m0 * DD + k1];
        } else if (m0 == 100) {
            if (k0 < 100) a0 = sWq[k0];
            if (k1 < 100) a2 = sWq[k1];
        }
        if (m1 < 100) {
            if (k0 < 100) a1 = Vw[m1 * DD + k0];
            if (k1 < 100) a3 = Vw[m1 * DD + k1];
        } else if (m1 == 100) {
            if (k0 < 100) a1 = sWq[k0];
            if (k1 < 100) a3 = sWq[k1];
        }
        float4 val = make_float4(a0, a1, a2, a3);
        *(float4*)(dst + (size_t)(w * KT + kt) * 128 + ln * 4) = val;
    }
}

// ---------------------------------------------------------------------------
// Kernel 2: W-in-registers tf32 GEMM, dual n-tile accumulator chains.
// D[e][r] = K[r][e]; col sums of squares via butterfly + per-warp partials;
// GEMM row 100 = score numerator.
// ---------------------------------------------------------------------------
#define F_V     0
#define F_PART  (F_V + 104 * AP)            // 7 * 112 = 784
#define F_DOT   (F_PART + 7 * 112)          // 112
#define F_ATT   (F_DOT + 112)               // 128
#define SMEM_FLOATS_TOT (F_ATT + 128)

__global__ __launch_bounds__(256, 3) void attn_kernel(
    const float* __restrict__ v,
    const float* __restrict__ Vb)
{
    extern __shared__ float smf[];
    float* sV    = smf + F_V;
    float* sPart = smf + F_PART;
    float* sdot  = smf + F_DOT;
    float* sAtt  = smf + F_ATT;

    int tid  = threadIdx.x;
    int warp = tid >> 5;
    int lane = tid & 31;
    int g    = lane >> 2;
    int tg   = lane & 3;

    int blk   = blockIdx.x;                  // 2048 blocks
    int b     = blk >> 6;
    int pair0 = (blk & 63) * PAIRS_PER_BLK;

    float cb = g_cb[b];

    // A fragments (W + w~) into registers, coalesced, once per block
    float4 aW[KT];
    float bias0 = 0.f, bias1 = 0.f, mval0 = 0.f, mval1 = 0.f;
    if (warp < 7) {
        const float4* src = (const float4*)(g_Af + (size_t)b * AF_PER_B
                                            + (size_t)warp * KT * 128);
        #pragma unroll
        for (int kt = 0; kt < KT; kt++) aW[kt] = src[kt * 32 + lane];
        int m0 = warp * 16 + g, m1 = m0 + 8;
        if (m0 < 100) { bias0 = Vb[m0]; mval0 = 1.f; }
        if (m1 < 100) { bias1 = Vb[m1]; mval1 = 1.f; }
    }

    // one-time pad zeroing of the v tile
    if (tid < 200) {
        int r = tid >> 1, h = tid & 1;
        *(float4*)(sV + r * AP + 100 + 4 * h) = make_float4(0.f, 0.f, 0.f, 0.f);
    }
    for (int i = tid; i < 4 * AP; i += 256) sV[100 * AP + i] = 0.f;

    for (int p = 0; p < PAIRS_PER_BLK; p++) {
        __syncthreads();

        int pp = b * 128 + pair0 + p;
        size_t vbase = (size_t)pp * 10000;
        for (int c = tid; c < 2500; c += 256) {
            int r = c / 25, dq = (c - r * 25) * 4;
            float4 val = *(const float4*)(v + vbase + r * DD + dq);
            *(float4*)(sV + r * AP + dq) = val;
        }
        __syncthreads();

        // ---- GEMM: warps 0..6; dual n-tile chains per iteration ----
        if (warp < 7) {
            #pragma unroll 1
            for (int np = 0; np < 6; np++) {
                int nt0 = 2 * np, nt1 = nt0 + 1;
                const float* br0 = sV + (nt0 * 8 + g) * AP + tg;
                const float* br1 = br0 + 8 * AP;
                float c0[4] = {0.f, 0.f, 0.f, 0.f};
                float c1[4] = {0.f, 0.f, 0.f, 0.f};
                #pragma unroll
                for (int kt = 0; kt < KT; kt++) {
                    float b00 = br0[kt * 8], b01 = br0[kt * 8 + 4];
                    float b10 = br1[kt * 8], b11 = br1[kt * 8 + 4];
                    mma_tf32(c0, (const float*)&aW[kt], b00, b01);
                    mma_tf32(c1, (const float*)&aW[kt], b10, b11);
                }
                // squares (rows = e), masked for invalid rows; cols all < 96
                float k0 = c0[0] + bias0, k1 = c0[1] + bias0;
                float k2 = c0[2] + bias1, k3 = c0[3] + bias1;
                float s0 = mval0 * k0 * k0 + mval1 * k2 * k2;
                float s1 = mval0 * k1 * k1 + mval1 * k3 * k3;
                float m0v = c1[0] + bias0, m1v = c1[1] + bias0;
                float m2v = c1[2] + bias1, m3v = c1[3] + bias1;
                float s2 = mval0 * m0v * m0v + mval1 * m2v * m2v;
                float s3 = mval0 * m1v * m1v + mval1 * m3v * m3v;
                #pragma unroll
                for (int o = 4; o <= 16; o <<= 1) {
                    s0 += __shfl_xor_sync(0xffffffffu, s0, o);
                    s1 += __shfl_xor_sync(0xffffffffu, s1, o);
                    s2 += __shfl_xor_sync(0xffffffffu, s2, o);
                    s3 += __shfl_xor_sync(0xffffffffu, s3, o);
                }
                if (g == 0) {
                    sPart[warp * 112 + nt0 * 8 + 2 * tg]     = s0;
                    sPart[warp * 112 + nt0 * 8 + 2 * tg + 1] = s1;
                    sPart[warp * 112 + nt1 * 8 + 2 * tg]     = s2;
                    sPart[warp * 112 + nt1 * 8 + 2 * tg + 1] = s3;
                }
                if (warp == 6 && g == 4) {     // GEMM row 100 = numerator
                    sdot[nt0 * 8 + 2 * tg]     = c0[0] + cb;
                    sdot[nt0 * 8 + 2 * tg + 1] = c0[1] + cb;
                    sdot[nt1 * 8 + 2 * tg]     = c1[0] + cb;
                    sdot[nt1 * 8 + 2 * tg + 1] = c1[1] + cb;
                }
            }
            {   // tail nt = 12
                const float* br = sV + (12 * 8 + g) * AP + tg;
                float c[4] = {0.f, 0.f, 0.f, 0.f};
                #pragma unroll
                for (int kt = 0; kt < KT; kt++)
                    mma_tf32(c, (const float*)&aW[kt], br[kt * 8], br[kt * 8 + 4]);
                float k0 = c[0] + bias0, k1 = c[1] + bias0;
                float k2 = c[2] + bias1, k3 = c[3] + bias1;
                float s0 = mval0 * k0 * k0 + mval1 * k2 * k2;
                float s1 = mval0 * k1 * k1 + mval1 * k3 * k3;
                #pragma unroll
                for (int o = 4; o <= 16; o <<= 1) {
                    s0 += __shfl_xor_sync(0xffffffffu, s0, o);
                    s1 += __shfl_xor_sync(0xffffffffu, s1, o);
                }
                if (g == 0) {
                    sPart[warp * 112 + 96 + 2 * tg]     = s0;
                    sPart[warp * 112 + 96 + 2 * tg + 1] = s1;
                }
                if (warp == 6 && g == 4) {
                    sdot[96 + 2 * tg]     = c[0] + cb;
                    sdot[96 + 2 * tg + 1] = c[1] + cb;
                }
            }
        }
        __syncthreads();

        // ---- softmax per s (warps 0,1); folds the 7-way partial sum ----
        if (warp < 2) {
            int s = warp;
            int rb = s * 50;
            float x0, x1;
            {
                int r = rb + lane;
                float nrm = 0.f;
                #pragma unroll
                for (int w = 0; w < 7; w++) nrm += sPart[w * 112 + r];
                float l2 = sqrtf(nrm);
                if (l2 == 0.0f) l2 = 1e-6f;
                float sc = sdot[r] / l2;
                sc = (sc == 0.0f) ? -10000.0f : sc;
                x0 = (sc > 0.0f) ? sc : 0.01f * sc;
            }
            x1 = -INFINITY;
            if (lane < NN - 32) {
                int r = rb + lane + 32;
                float nrm = 0.f;
                #pragma unroll
                for (int w = 0; w < 7; w++) nrm += sPart[w * 112 + r];
                float l2 = sqrtf(nrm);
                if (l2 == 0.0f) l2 = 1e-6f;
                float sc = sdot[r] / l2;
                sc = (sc == 0.0f) ? -10000.0f : sc;
                x1 = (sc > 0.0f) ? sc : 0.01f * sc;
            }
            float m = fmaxf(x0, x1);
            #pragma unroll
            for (int o = 16; o; o >>= 1) m = fmaxf(m, __shfl_xor_sync(0xffffffffu, m, o));
            float e0 = expf(x0 - m);
            float e1 = (lane < NN - 32) ? expf(x1 - m) : 0.0f;
            float sm = e0 + e1;
            #pragma unroll
            for (int o = 16; o; o >>= 1) sm += __shfl_xor_sync(0xffffffffu, sm, o);
            float inv = 1.0f / sm;
            float a0 = e0 * inv;
            if (a0 == (1.0f / 50.0f)) a0 = 0.0f;
            float a1 = 0.0f;
            if (lane < NN - 32) {
                a1 = e1 * inv;
                if (a1 == (1.0f / 50.0f)) a1 = 0.0f;
            }
            sAtt[rb + lane] = a0;
            if (lane < NN - 32) sAtt[rb + lane + 32] = a1;
            float sg = a0 + a1;
            #pragma unroll
            for (int o = 16; o; o >>= 1) sg += __shfl_xor_sync(0xffffffffu, sg, o);
            if (lane == 0) g_sig[pp * 2 + s] = sg;
        }
        __syncthreads();

        // ---- t[s][e] = sum_n att[s][n] * v[s*50+n][e]  (exact fp32) ----
        int s = tid >> 7;
        int e = tid & 127;
        if (e < 100) {
            float acc = 0.f;
            const float* ab = sAtt + s * 50;
            const float* kb = sV + (s * 50) * AP + e;
            #pragma unroll 5
            for (int n = 0; n < NN; n++) acc += ab[n] * kb[n * AP];
            g_T[(size_t)(pp * 2 + s) * DD + e] = acc;
        }
    }
}

// ---------------------------------------------------------------------------
// Kernel 3: out[r][e] = sum_d T[r][d] * W[e][d] + sig[r] * Vb[e]
// Transposes W into smem (stride 101, conflict-free both ways).
// ---------------------------------------------------------------------------
#define OP_ROWS 16
#define WS 101
__global__ __launch_bounds__(128) void out_proj(
    const float* __restrict__ Vw,
    const float* __restrict__ Vb,
    float* __restrict__ out)
{
    __shared__ float sW[DD * WS];          // sW[d*101+e] = Vw[e*100+d]
    __shared__ float sT[OP_ROWS * DD];
    __shared__ float sS[OP_ROWS];

    int tid = threadIdx.x;
    int r0  = blockIdx.x * OP_ROWS;

    for (int i = tid; i < DD * DD; i += 128) {
        int e = i / DD, d = i - e * DD;     // coalesced LDG, conflict-free STS
        sW[d * WS + e] = Vw[i];
    }
    {
        const float4* tsrc = (const float4*)(g_T + (size_t)r0 * DD);
        float4* tdst = (float4*)sT;
        for (int i = tid; i < OP_ROWS * DD / 4; i += 128) tdst[i] = tsrc[i];
        if (tid < OP_ROWS) sS[tid] = g_sig[r0 + tid];
    }
    __syncthreads();

    int e = tid;
    if (e < DD) {
        float be = Vb[e];
        float acc[OP_ROWS];
        #pragma unroll
        for (int j = 0; j < OP_ROWS; j++) acc[j] = sS[j] * be;
        #pragma unroll 2
        for (int d = 0; d < DD; d++) {
            float w = sW[d * WS + e];
            #pragma unroll
            for (int j = 0; j < OP_ROWS; j++) acc[j] += sT[j * DD + d] * w;
        }
        #pragma unroll
        for (int j = 0; j < OP_ROWS; j++)
            out[(size_t)(r0 + j) * DD + e] = acc[j];
    }
}

// ---------------------------------------------------------------------------
extern "C" void kernel_launch(void* const* d_in, const int* in_sizes, int n_in,
                              void* d_out, int out_size)
{
    // metadata order: input_ent, q, k, v, Q_w, Q_b, V_w, V_b
    const float* q  = (const float*)d_in[1];
    const float* v  = (const float*)d_in[3];
    const float* Qw = (const float*)d_in[4];
    const float* Qb = (const float*)d_in[5];
    const float* Vw = (const float*)d_in[6];
    const float* Vb = (const float*)d_in[7];
    float* out = (float*)d_out;

    qproj_a<<<BB * DD, 128>>>(q, Qw, Qb);
    qproj_b<<<BB, 128>>>(Vw, Vb);

    size_t smem_bytes = SMEM_FLOATS_TOT * sizeof(float);
    cudaFuncSetAttribute(attn_kernel, cudaFuncAttributeMaxDynamicSharedMemorySize,
                         (int)smem_bytes);
    attn_kernel<<<BB * SS / 2 / PAIRS_PER_BLK, 256, smem_bytes>>>(v, Vb);

    out_proj<<<BB * SS / OP_ROWS, 128>>>(Vw, Vb, out);
}